// round 13
// baseline (speedup 1.0000x reference)
#include <cuda_runtime.h>
#include <cuda_fp16.h>

// y = FWHT(G * Perm(FWHT(x * B))), orthonormal, L = 16384, fused one-pass.
//
// ROW-PAIR packing: one CTA (1024 threads) processes rows (2b, 2b+1); every
// f32x2 register and every smem half2 word holds (rowA[n], rowB[n]) for ONE
// index n. All butterflies packed (no scalar stage); the gather is one u32
// LDS per n (both rows at once). 16 words/thread = 4 reg bits + 10 thread
// bits (lanes = t0..t4). Bit plan per FWHT (value space n, 14 bits):
//   P1: regs {n0,n1,n12,n13}; threads t0..t9 -> n2..n11 (coalesced float4 IO)
//   P2: regs {n2,n3,n8,n9};  threads -> n0,n1(t0,t1) n4..n7(t2..t5) n10..n13(t6..t9)
//   P3: regs {n4..n7}; shfl n10(lane t2, mask4), n11(lane t3, mask8);
//       threads -> n0,n1(t0,t1) n10,n11(t2,t3) n2(t4) n3(t5) n8,n9(t6,t7) n12,n13(t8,t9)
// Swizzle sw(n) = n ^ (n5<<2) ^ ((n6^n10)<<3) ^ (n11<<4)  (GF(2)-linear):
// verified conflict-free for P1 (128b per 8-lane quarter: banks t0,t1,t2),
// P2 (banks t0,t1,t3,t4,t2), P3/pass5 (banks t0,t1,t4,t2,t3).
// Row flow: P1->A | P2 in A | P3 ld A (+2 shfl bflys), pass5 z=y1*Gp st B |
// gather B via u16 Pisw (+2 shfl bflys) -> P3' st A (NO barrier: A idle) |
// P2' in A | P1' -> gmem.   5 barriers per 2 rows.
// smem = A(64KB) + B(64KB) = 128KB, 1 CTA/SM, RF exactly full (1024x64).
// Prep: Bbits sign table; Gph[Pi[n]] = half(G[n]/16384); Pisw[n] = sw(Pi[n]) u16.

#define L_N        16384
#define NT         1024
#define SMEM_BYTES (2 * L_N * 4)   // 131072: A + B, one u32 word per n

typedef unsigned long long ull;

__device__ __align__(16) unsigned       g_Bbits[L_N / 32];
__device__ __align__(16) unsigned short g_Pisw[L_N];
__device__ __align__(16) __half         g_Gph[L_N];

__device__ __forceinline__ int sw(int n) {
    return n ^ ((((n >> 5) & 1) << 2)
              ^ ((((n >> 6) ^ (n >> 10)) & 1) << 3)
              ^ (((n >> 11) & 1) << 4));
}

// ---- packed f32x2 helpers ----
__device__ __forceinline__ ull padd(ull a, ull b) {
    ull r; asm("add.rn.f32x2 %0, %1, %2;" : "=l"(r) : "l"(a), "l"(b)); return r;
}
__device__ __forceinline__ ull pmul(ull a, ull b) {
    ull r; asm("mul.rn.f32x2 %0, %1, %2;" : "=l"(r) : "l"(a), "l"(b)); return r;
}
__device__ __forceinline__ ull psub(ull a, ull b) {   // a - b
    const ull N1 = 0xBF800000BF800000ULL;
    ull r; asm("fma.rn.f32x2 %0, %1, %2, %3;" : "=l"(r) : "l"(b), "l"(N1), "l"(a));
    return r;
}
__device__ __forceinline__ ull pk2(float lo, float hi) {
    ull r; asm("mov.b64 %0, {%1, %2};" : "=l"(r) : "f"(lo), "f"(hi)); return r;
}
__device__ __forceinline__ float2 upk2(ull v) {
    float2 f; asm("mov.b64 {%0, %1}, %2;" : "=f"(f.x), "=f"(f.y) : "l"(v)); return f;
}
__device__ __forceinline__ ull h2_to_p(unsigned u) {
    __half2 h = *reinterpret_cast<__half2*>(&u);
    float2 f = __half22float2(h);
    return pk2(f.x, f.y);
}
__device__ __forceinline__ unsigned p_to_h2(ull v) {
    float2 f = upk2(v);
    __half2 h = __float22half2_rn(f);
    return *reinterpret_cast<unsigned*>(&h);
}

__device__ __forceinline__ void bflyp(ull &A, ull &B) {
    ull s_ = padd(A, B);
    ull d_ = psub(A, B);
    A = s_; B = d_;
}

__device__ __forceinline__ void fwht16p(ull W[16]) {
#pragma unroll
    for (int m = 1; m < 16; m <<= 1) {
#pragma unroll
        for (int i = 0; i < 16; i++) {
            if ((i & m) == 0) bflyp(W[i], W[i | m]);
        }
    }
}

// swizzle deltas for phase-local word bits (constants under full unroll)
__device__ __forceinline__ int d2c(int w) {   // w -> {n2,n3,n8,n9}; no f terms
    return ((w & 1) << 2) | (((w >> 1) & 1) << 3)
         | (((w >> 2) & 1) << 8) | (((w >> 3) & 1) << 9);
}
__device__ __forceinline__ int d3c(int w) {   // w -> {n4..n7}; n5->f2, n6->f3
    return (w << 4) ^ (((w >> 1) & 1) << 2) ^ (((w >> 2) & 1) << 3);
}

__global__ void prep_kernel(const float* __restrict__ Gv,
                            const int* __restrict__ Pi,
                            const float* __restrict__ Bv) {
    int n = blockIdx.x * blockDim.x + threadIdx.x;   // 16384 threads
    int p = Pi[n];
    g_Pisw[n] = (unsigned short)sw(p);
    g_Gph[p]  = __float2half(Gv[n] * (1.0f / 16384.0f));
    unsigned sb  = __float_as_uint(Bv[n]) >> 31;
    unsigned bal = __ballot_sync(0xffffffffu, sb);
    if ((n & 31) == 0) g_Bbits[n >> 5] = bal;
}

__global__ __launch_bounds__(NT, 1)
void fwht_fused_kernel(const float* __restrict__ x,
                       float* __restrict__ out) {
    extern __shared__ unsigned s32[];
    unsigned* const sA = s32;          // data buffer A (one u32 per n)
    unsigned* const sB = s32 + L_N;    // z buffer (pass5 / gather)
    const int t = threadIdx.x;         // 10 bits
    const size_t rowA = (size_t)blockIdx.x * 2;

    ull W[16];

    // phase base addresses (swizzled once)
    const int base1 = sw(t << 2);                       // P1: n = t<<2 | g<<12
    const int p2q = (t & 3) | (((t >> 2) & 0xF) << 4) | ((t >> 6) << 10);
    const int base2 = sw(p2q);
    const int p3q = (t & 3) | (((t >> 2) & 3) << 10) | (((t >> 4) & 1) << 2)
                  | (((t >> 5) & 1) << 3) | (((t >> 6) & 3) << 8)
                  | ((t >> 8) << 12);
    const int base3 = sw(p3q);

    // ===== FWHT#1 P1: regs {n0,n1,n12,n13}; coalesced loads; B sign XOR =====
    {
        const float4* __restrict__ x4A =
            reinterpret_cast<const float4*>(x + rowA * L_N);
        const float4* __restrict__ x4B = x4A + (L_N / 4);
#pragma unroll
        for (int g = 0; g < 4; g++) {
            float4 xa = x4A[(g << 10) + t];
            float4 xb = x4B[(g << 10) + t];
            unsigned u = g_Bbits[(t >> 3) | (g << 7)] >> ((t & 7) << 2);
            unsigned s0 = (u & 1u) << 31, s1 = (u & 2u) << 30;
            unsigned s2 = (u & 4u) << 29, s3 = (u & 8u) << 28;
            W[4 * g + 0] = pk2(__uint_as_float(__float_as_uint(xa.x) ^ s0),
                               __uint_as_float(__float_as_uint(xb.x) ^ s0));
            W[4 * g + 1] = pk2(__uint_as_float(__float_as_uint(xa.y) ^ s1),
                               __uint_as_float(__float_as_uint(xb.y) ^ s1));
            W[4 * g + 2] = pk2(__uint_as_float(__float_as_uint(xa.z) ^ s2),
                               __uint_as_float(__float_as_uint(xb.z) ^ s2));
            W[4 * g + 3] = pk2(__uint_as_float(__float_as_uint(xa.w) ^ s3),
                               __uint_as_float(__float_as_uint(xb.w) ^ s3));
        }
    }
    fwht16p(W);   // bits {n0, n1, n12, n13}
#pragma unroll
    for (int g = 0; g < 4; g++) {
        uint4 v;
        v.x = p_to_h2(W[4 * g + 0]);
        v.y = p_to_h2(W[4 * g + 1]);
        v.z = p_to_h2(W[4 * g + 2]);
        v.w = p_to_h2(W[4 * g + 3]);
        *reinterpret_cast<uint4*>(&sA[base1 ^ (g << 12)]) = v;
    }
    __syncthreads();

    // ===== FWHT#1 P2: regs {n2,n3,n8,n9} (in-place in A) =====
#pragma unroll
    for (int w = 0; w < 16; w++) W[w] = h2_to_p(sA[base2 ^ d2c(w)]);
    fwht16p(W);
#pragma unroll
    for (int w = 0; w < 16; w++) sA[base2 ^ d2c(w)] = p_to_h2(W[w]);
    __syncthreads();

    // ===== FWHT#1 P3: shfl bflys n10 (mask4), n11 (mask8) + regs {n4..n7} =====
#pragma unroll
    for (int w = 0; w < 16; w++) {
        unsigned pw = sA[base3 ^ d3c(w)];
        unsigned qw = __shfl_xor_sync(0xffffffffu, pw, 4);    // n10 partner
        ull A = h2_to_p(pw), Bp = h2_to_p(qw);
        ull v1 = (t & 4) ? psub(Bp, A) : padd(A, Bp);
        ull v2 = __shfl_xor_sync(0xffffffffu, v1, 8);         // n11 partner
        W[w] = (t & 8) ? psub(v2, v1) : padd(v1, v2);
    }
    fwht16p(W);

    // ===== pass 5: z = y1 * Gp (G + 1/16384 folded, fp16), store to B =====
#pragma unroll
    for (int w = 0; w < 16; w++) {
        float gf = __half2float(g_Gph[p3q | (w << 4)]);
        sB[base3 ^ d3c(w)] = p_to_h2(pmul(W[w], pk2(gf, gf)));
    }
    __syncthreads();

    // ===== gather from B (u16 Pisw addrs) + shfl bflys n10, n11 =====
#pragma unroll
    for (int w = 0; w < 16; w++) {
        unsigned pp = g_Pisw[p3q | (w << 4)];
        unsigned pw = sB[pp];
        unsigned qw = __shfl_xor_sync(0xffffffffu, pw, 4);
        ull A = h2_to_p(pw), Bp = h2_to_p(qw);
        ull v1 = (t & 4) ? psub(Bp, A) : padd(A, Bp);
        ull v2 = __shfl_xor_sync(0xffffffffu, v1, 8);
        W[w] = (t & 8) ? psub(v2, v1) : padd(v1, v2);
    }
    // NO barrier: P3' stores go to A, whose last reads (P3 loads) completed
    // before the pass-5 barrier; gather touched only B.

    // ===== FWHT#2 P3': regs {n4..n7}, store to A =====
    fwht16p(W);
#pragma unroll
    for (int w = 0; w < 16; w++) sA[base3 ^ d3c(w)] = p_to_h2(W[w]);
    __syncthreads();

    // ===== FWHT#2 P2': regs {n2,n3,n8,n9} (in-place in A) =====
#pragma unroll
    for (int w = 0; w < 16; w++) W[w] = h2_to_p(sA[base2 ^ d2c(w)]);
    fwht16p(W);
#pragma unroll
    for (int w = 0; w < 16; w++) sA[base2 ^ d2c(w)] = p_to_h2(W[w]);
    __syncthreads();

    // ===== FWHT#2 P1': regs {n0,n1,n12,n13}; coalesced float4 stores =====
#pragma unroll
    for (int g = 0; g < 4; g++) {
        uint4 v = *reinterpret_cast<const uint4*>(&sA[base1 ^ (g << 12)]);
        W[4 * g + 0] = h2_to_p(v.x);
        W[4 * g + 1] = h2_to_p(v.y);
        W[4 * g + 2] = h2_to_p(v.z);
        W[4 * g + 3] = h2_to_p(v.w);
    }
    fwht16p(W);
    {
        float4* __restrict__ o4A = reinterpret_cast<float4*>(out + rowA * L_N);
        float4* __restrict__ o4B = o4A + (L_N / 4);
#pragma unroll
        for (int g = 0; g < 4; g++) {
            float2 f0 = upk2(W[4 * g + 0]);
            float2 f1 = upk2(W[4 * g + 1]);
            float2 f2 = upk2(W[4 * g + 2]);
            float2 f3 = upk2(W[4 * g + 3]);
            o4A[(g << 10) + t] = make_float4(f0.x, f1.x, f2.x, f3.x);
            o4B[(g << 10) + t] = make_float4(f0.y, f1.y, f2.y, f3.y);
        }
    }
}

extern "C" void kernel_launch(void* const* d_in, const int* in_sizes, int n_in,
                              void* d_out, int out_size) {
    const float* x  = (const float*)d_in[0];
    const float* B  = (const float*)d_in[1];
    const float* G  = (const float*)d_in[2];
    const int*   Pi = (const int*)d_in[3];
    float* out = (float*)d_out;

    int rows = in_sizes[0] / L_N;

    cudaFuncSetAttribute(fwht_fused_kernel,
                         cudaFuncAttributeMaxDynamicSharedMemorySize, SMEM_BYTES);

    prep_kernel<<<L_N / 256, 256>>>(G, Pi, B);
    fwht_fused_kernel<<<rows / 2, NT, SMEM_BYTES>>>(x, out);
}

// round 16
// speedup vs baseline: 1.2330x; 1.2330x over previous
#include <cuda_runtime.h>
#include <cuda_fp16.h>

// y = FWHT(G * Perm(FWHT(x * B))), orthonormal, L = 16384, fused one-pass.
//
// Grid = 4096 (one row/CTA), 512 thr/CTA, 2 CTA/SM (co-residency beats
// barrier-count: row-pair/1024-thread variant measured slower).
// fp16 SMEM data in TWO buffers (A,B; 64KB total), fp32 packed f32x2 math.
// Bit plan per FWHT (word space q = n>>1):
//   P1: {n0 scalar, n1,n11,n12,n13 packed}; lanes = n2..n10 (coalesced f4)
//   P2: word bits {q1,q2,q7,q8} = {n2,n3,n8,n9} (in-place in A)
//   P3: word bits {q3..q6} = {n4..n7}; n10 via __shfl_xor(word,16)
// Swizzle swq (GF(2)-linear) keeps all structured passes conflict-free.
// Row flow: P1->A | P2 in A | [prefetch 16x Pisw u32 -> pp regs] P3 ld A,
// z=y1*Gp st B | gather B (addrs from pp, pure LDS) -> P3' st A (NO barrier:
// A idle since pass-5 barrier) | P2' in A | P1' -> gmem.  5 barriers/row.
// R14: Pisw prefetch hoisted ~2 passes ahead of the gather so the ~600-cyc
// global latency overlaps P3+pass5+barrier instead of serializing after it.
// Register budget: W 16 ull (32) + pp 16 u32 (16) = 48 data regs < 64.
// Prep: Bbits sign table; Gph[Pi[n]] = half(G[n]/16384); Pisw[n] = swizzled
// half-address of Pi[n] (u16).

#define L_N        16384
#define NQ         (L_N / 2)            // 8192 words per buffer
#define NT         512
#define SMEM_BYTES (2 * NQ * 4)         // 65536 (A + B)

typedef unsigned long long ull;

__device__ __align__(16) unsigned       g_Bbits[L_N / 32];
__device__ __align__(16) unsigned short g_Pisw[L_N];
__device__ __align__(16) __half         g_Gph[L_N];

__device__ __forceinline__ int swq(int q) {
    int f = (((q >> 5) & 1) << 1) ^ (((q >> 9) & 1) << 2) ^ (((q >> 7) & 1) << 3)
          ^ ((((q >> 2) ^ (q >> 8)) & 1) << 4);
    return q ^ f;
}

// ---- packed f32x2 helpers ----
__device__ __forceinline__ ull padd(ull a, ull b) {
    ull r; asm("add.rn.f32x2 %0, %1, %2;" : "=l"(r) : "l"(a), "l"(b)); return r;
}
__device__ __forceinline__ ull pmul(ull a, ull b) {
    ull r; asm("mul.rn.f32x2 %0, %1, %2;" : "=l"(r) : "l"(a), "l"(b)); return r;
}
__device__ __forceinline__ ull psub(ull a, ull b) {   // a - b
    const ull N1 = 0xBF800000BF800000ULL;
    ull r; asm("fma.rn.f32x2 %0, %1, %2, %3;" : "=l"(r) : "l"(b), "l"(N1), "l"(a));
    return r;
}
__device__ __forceinline__ ull pk2(float lo, float hi) {
    ull r; asm("mov.b64 %0, {%1, %2};" : "=l"(r) : "f"(lo), "f"(hi)); return r;
}
__device__ __forceinline__ float2 upk2(ull v) {
    float2 f; asm("mov.b64 {%0, %1}, %2;" : "=f"(f.x), "=f"(f.y) : "l"(v)); return f;
}
__device__ __forceinline__ ull h2_to_p(unsigned u) {
    __half2 h = *reinterpret_cast<__half2*>(&u);
    float2 f = __half22float2(h);
    return pk2(f.x, f.y);
}
__device__ __forceinline__ unsigned p_to_h2(ull v) {
    float2 f = upk2(v);
    __half2 h = __float22half2_rn(f);
    return *reinterpret_cast<unsigned*>(&h);
}

__device__ __forceinline__ void bflyp(ull &A, ull &B) {
    ull s_ = padd(A, B);
    ull d_ = psub(A, B);
    A = s_; B = d_;
}

__device__ __forceinline__ void fwht16p(ull W[16]) {
#pragma unroll
    for (int m = 1; m < 16; m <<= 1) {
#pragma unroll
        for (int i = 0; i < 16; i++) {
            if ((i & m) == 0) bflyp(W[i], W[i | m]);
        }
    }
}

// swizzle deltas for phase-local word bits (constants under full unroll)
__device__ __forceinline__ int d2c(int w) {   // wbits {q1,q2,q7,q8}
    int wb = ((w & 1) << 1) | (((w >> 1) & 1) << 2) | (((w >> 2) & 1) << 7)
           | (((w >> 3) & 1) << 8);
    int f = ((((w >> 1) ^ (w >> 3)) & 1) << 4) ^ (((w >> 2) & 1) << 3);
    return wb ^ f;
}
__device__ __forceinline__ int d3c(int w) {   // wbits {q3..q6}; q5 -> b1
    return (w << 3) ^ (((w >> 2) & 1) << 1);
}

__global__ void prep_kernel(const float* __restrict__ Gv,
                            const int* __restrict__ Pi,
                            const float* __restrict__ Bv) {
    int n = blockIdx.x * blockDim.x + threadIdx.x;   // 16384 threads
    int p = Pi[n];
    g_Pisw[n] = (unsigned short)((swq(p >> 1) << 1) | (p & 1));
    g_Gph[p]  = __float2half(Gv[n] * (1.0f / 16384.0f));
    unsigned sb  = __float_as_uint(Bv[n]) >> 31;
    unsigned bal = __ballot_sync(0xffffffffu, sb);
    if ((n & 31) == 0) g_Bbits[n >> 5] = bal;
}

__global__ __launch_bounds__(NT, 2)
void fwht_fused_kernel(const float* __restrict__ x,
                       float* __restrict__ out) {
    extern __shared__ unsigned s32[];
    unsigned* const sA = s32;          // data buffer A
    unsigned* const sB = s32 + NQ;     // z buffer (pass5 / gather)
    const int t = threadIdx.x;
    const size_t row = blockIdx.x;

    ull W[16];

    // phase base words (swizzled once; phase-local bits XORed per access)
    const int base1 = swq(t << 1);
    const int p2q = (t & 1) | (((t >> 1) & 7) << 3) | (((t >> 4) & 1) << 9)
                  | (((t >> 5) & 1) << 6) | (((t >> 6) & 7) << 10);
    const int base2 = swq(p2q);
    const int p3q = (t & 7) | (((t >> 3) & 1) << 7) | (((t >> 4) & 1) << 9)
                  | (((t >> 5) & 1) << 8) | (((t >> 6) & 7) << 10);
    const int base3 = swq(p3q);

    // ===== FWHT#1 P1: scalar n0 stage at load, packed {n1,n11,n12,n13} =====
    {
        const float4* __restrict__ x4 =
            reinterpret_cast<const float4*>(x + row * L_N);
#pragma unroll
        for (int k = 0; k < 8; k++) {
            float4 xv = x4[(k << 9) + t];
            unsigned u = g_Bbits[(k << 6) + (t >> 3)] >> ((t & 7) << 2);
            float a = __uint_as_float(__float_as_uint(xv.x) ^ ((u & 1u) << 31));
            float b = __uint_as_float(__float_as_uint(xv.y) ^ ((u & 2u) << 30));
            float c = __uint_as_float(__float_as_uint(xv.z) ^ ((u & 4u) << 29));
            float d = __uint_as_float(__float_as_uint(xv.w) ^ ((u & 8u) << 28));
            W[2 * k]     = pk2(a + b, a - b);
            W[2 * k + 1] = pk2(c + d, c - d);
        }
    }
    fwht16p(W);
#pragma unroll
    for (int k = 0; k < 8; k++) {
        uint2 v;
        v.x = p_to_h2(W[2 * k]);
        v.y = p_to_h2(W[2 * k + 1]);
        *reinterpret_cast<uint2*>(&sA[base1 ^ (k << 10)]) = v;
    }
    __syncthreads();

    // ===== FWHT#1 P2: word bits {q1,q2,q7,q8} (in-place in A) =====
#pragma unroll
    for (int w = 0; w < 16; w++) W[w] = h2_to_p(sA[base2 ^ d2c(w)]);
    fwht16p(W);
#pragma unroll
    for (int w = 0; w < 16; w++) sA[base2 ^ d2c(w)] = p_to_h2(W[w]);
    __syncthreads();

    // ===== Pisw prefetch: issue 16 independent global loads ~2 passes early =====
    unsigned pp[16];
#pragma unroll
    for (int w = 0; w < 16; w++) {
        pp[w] = __ldg(reinterpret_cast<const unsigned*>(
            &g_Pisw[(p3q | (w << 3)) << 1]));
    }

    // ===== FWHT#1 P3: shfl butterfly (n10) + word bits {q3..q6} =====
#pragma unroll
    for (int w = 0; w < 16; w++) {
        unsigned pw = sA[base3 ^ d3c(w)];
        unsigned qw = __shfl_xor_sync(0xffffffffu, pw, 16);
        ull A = h2_to_p(pw), Bp = h2_to_p(qw);
        W[w] = (t & 16) ? psub(Bp, A) : padd(A, Bp);
    }
    fwht16p(W);

    // ===== pass 5: z = y1 * Gp (G + 1/16384 folded, fp16), store to B =====
#pragma unroll
    for (int w = 0; w < 16; w++) {
        unsigned gph = *reinterpret_cast<const unsigned*>(
            &g_Gph[(p3q | (w << 3)) << 1]);
        sB[base3 ^ d3c(w)] = p_to_h2(pmul(W[w], h2_to_p(gph)));
    }
    __syncthreads();

    // ===== gather from B (addrs from pp regs, pure LDS) + shfl bfly (n10) =====
    {
        const unsigned short* __restrict__ shB =
            reinterpret_cast<const unsigned short*>(sB);
#pragma unroll
        for (int w = 0; w < 16; w++) {
            unsigned h0 = shB[pp[w] & 0xffffu];
            unsigned h1 = shB[pp[w] >> 16];
            unsigned pw = __byte_perm(h0, h1, 0x5410);
            unsigned qw = __shfl_xor_sync(0xffffffffu, pw, 16);
            ull A = h2_to_p(pw), Bp = h2_to_p(qw);
            W[w] = (t & 16) ? psub(Bp, A) : padd(A, Bp);
        }
    }
    // NO barrier here: P3' stores go to A, whose last reads (P3 loads)
    // completed before the pass-5 barrier; gather touched only B.

    // ===== FWHT#2 P3: word bits {q3..q6}, store to A =====
    fwht16p(W);
#pragma unroll
    for (int w = 0; w < 16; w++) sA[base3 ^ d3c(w)] = p_to_h2(W[w]);
    __syncthreads();

    // ===== FWHT#2 P2: word bits {q1,q2,q7,q8} (in-place in A) =====
#pragma unroll
    for (int w = 0; w < 16; w++) W[w] = h2_to_p(sA[base2 ^ d2c(w)]);
    fwht16p(W);
#pragma unroll
    for (int w = 0; w < 16; w++) sA[base2 ^ d2c(w)] = p_to_h2(W[w]);
    __syncthreads();

    // ===== FWHT#2 P1: packed {n1,n11,n12,n13}, scalar n0, f4 store =====
#pragma unroll
    for (int k = 0; k < 8; k++) {
        uint2 v = *reinterpret_cast<const uint2*>(&sA[base1 ^ (k << 10)]);
        W[2 * k]     = h2_to_p(v.x);
        W[2 * k + 1] = h2_to_p(v.y);
    }
    fwht16p(W);
    {
        float4* __restrict__ o4 = reinterpret_cast<float4*>(out + row * L_N);
#pragma unroll
        for (int k = 0; k < 8; k++) {
            float2 f0 = upk2(W[2 * k]);
            float2 f1 = upk2(W[2 * k + 1]);
            o4[(k << 9) + t] = make_float4(f0.x + f0.y, f0.x - f0.y,
                                           f1.x + f1.y, f1.x - f1.y);
        }
    }
}

extern "C" void kernel_launch(void* const* d_in, const int* in_sizes, int n_in,
                              void* d_out, int out_size) {
    const float* x  = (const float*)d_in[0];
    const float* B  = (const float*)d_in[1];
    const float* G  = (const float*)d_in[2];
    const int*   Pi = (const int*)d_in[3];
    float* out = (float*)d_out;

    int rows = in_sizes[0] / L_N;

    cudaFuncSetAttribute(fwht_fused_kernel,
                         cudaFuncAttributeMaxDynamicSharedMemorySize, SMEM_BYTES);

    prep_kernel<<<L_N / 256, 256>>>(G, Pi, B);
    fwht_fused_kernel<<<rows, NT, SMEM_BYTES>>>(x, out);
}